// round 16
// baseline (speedup 1.0000x reference)
#include <cuda_runtime.h>

#define HSZ  512
#define TMAX 513
#define NBUILD 80

// tables: 0=feat(+bo/2), 1=q, 2=k, 3=v@Wo   (token row = T[c0] + T[c1])
__device__ float g_T[4][TMAX * 64];
__device__ int g_seal[TMAX];   // zero-init; 1 once row c is written

// ---------------------------------------------------------------------------
// Packed hash entry: (key << 10) | slot.  EMPTY = -1, PENDING slot = 0x3FF.
__device__ __forceinline__ int insert_pair(int key, int* tab, int* counter, int* keys)
{
    unsigned h = ((unsigned)key * 2654435761u) >> 23;   // 9-bit hash
    const int PEND = (key << 10) | 0x3FF;
    while (true) {
        int e = tab[h];
        if (e == -1) e = atomicCAS(&tab[h], -1, PEND);
        if (e == -1) {
            int s = atomicAdd(counter, 1);
            keys[s] = key;
            __threadfence_block();
            atomicExch(&tab[h], (key << 10) | s);
            return s;
        }
        if ((e >> 10) == key) {
            int s = e & 0x3FF;
            while (s == 0x3FF) s = ((volatile int*)tab)[h] & 0x3FF;
            return s;
        }
        h = (h + 1) & (HSZ - 1);
    }
}

__device__ __forceinline__ int insert_pair_agg(int key, int* tab, int* counter,
                                               int* keys, int* mult)
{
    unsigned peers = __match_any_sync(0xffffffffu, key);
    int leader = __ffs(peers) - 1;
    int s = 0;
    if ((int)(threadIdx.x & 31) == leader) {
        s = insert_pair(key, tab, counter, keys);
        if (mult) atomicAdd(&mult[s], __popc(peers));
    }
    return __shfl_sync(0xffffffffu, s, leader);
}

// Shared plan (worker): hist[2000] hashA[512] hashO[512] a_keys[512] o_keys[512]
//   o_mult[512] counters[96] (ctr8+marks17+pad+cvals64) tok_as u16[512]
//   ctx2q[4096] Ebuf[2048] Vbuf[2048] colmax[64] part[256] cvec[128]
#define NINT (2000 + 2 * HSZ + 3 * 512 + 96 + 256)
#define NFLT (4096 + 2048 + 2048 + 64 + 256 + 128)
#define SMEM_BYTES ((NINT + NFLT) * 4)

__global__ void __launch_bounds__(256, 4) fused_kernel(
    const int* __restrict__ src, const int* __restrict__ dst,
    const float* __restrict__ w1, const float* __restrict__ b1,
    const float* __restrict__ w2, const float* __restrict__ b2,
    const float* __restrict__ Wq, const float* __restrict__ Wk,
    const float* __restrict__ Wv, const float* __restrict__ Wo,
    const float* __restrict__ bo,
    const float* __restrict__ lng, const float* __restrict__ lnb,
    float* __restrict__ out)
{
    extern __shared__ int sm[];
    const int t = threadIdx.x;

    // ============ builder blocks (0..79): rows c = bid + 80k ===============
    // Pass A: row c=bid only (hot small counts seal ~0.5us in).
    // Pass B: remaining 5-6 rows batched.
    if (blockIdx.x < NBUILD) {
        float* R  = (float*)sm;         // 7*64
        float* FE = R + 448;            // 7*64
        float* VT = FE + 448;           // 7*64
        const int g = t & 63, j = t >> 6;            // j in 0..3
        const int base = blockIdx.x;
        const int nr_total = (base < 33) ? 7 : 6;    // 513 = 33*7 + 47*6

        for (int pass = 0; pass < 2; pass++) {
            const int k0 = (pass == 0) ? 0 : 1;
            const int nr = (pass == 0) ? 1 : (nr_total - 1);
            if (nr <= 0) break;
            for (int idx = t; idx < nr * 64; idx += 256) {
                int k = idx >> 6, f = idx & 63;
                R[idx] = fmaxf((float)(base + 80 * (k0 + k)) * w1[f] + b1[f], 0.f);
            }
            __syncthreads();
            for (int r = j; r < nr; r += 4) {
                float a0 = 0.f, a1 = 0.f, a2 = 0.f, a3 = 0.f;
#pragma unroll
                for (int f = 0; f < 64; f += 4) {
                    a0 += R[r * 64 + f]     * w2[f * 64 + g];
                    a1 += R[r * 64 + f + 1] * w2[(f + 1) * 64 + g];
                    a2 += R[r * 64 + f + 2] * w2[(f + 2) * 64 + g];
                    a3 += R[r * 64 + f + 3] * w2[(f + 3) * 64 + g];
                }
                float acc = b2[g] + ((a0 + a1) + (a2 + a3));
                FE[r * 64 + g] = acc;
                g_T[0][(base + 80 * (k0 + r)) * 64 + g] = acc + 0.5f * bo[g];
            }
            __syncthreads();
            for (int r = j; r < nr; r += 4) {
                float aq = 0.f, ak = 0.f, av = 0.f;
#pragma unroll 8
                for (int f = 0; f < 64; f++) {
                    float fe = FE[r * 64 + f];
                    aq += fe * Wq[f * 64 + g];
                    ak += fe * Wk[f * 64 + g];
                    av += fe * Wv[f * 64 + g];
                }
                int c = base + 80 * (k0 + r);
                g_T[1][c * 64 + g] = aq;
                g_T[2][c * 64 + g] = ak;
                VT[r * 64 + g] = av;
            }
            __syncthreads();
            for (int r = j; r < nr; r += 4) {
                float a0 = 0.f, a1 = 0.f, a2 = 0.f, a3 = 0.f;
#pragma unroll
                for (int f = 0; f < 64; f += 4) {
                    a0 += VT[r * 64 + f]     * Wo[f * 64 + g];
                    a1 += VT[r * 64 + f + 1] * Wo[(f + 1) * 64 + g];
                    a2 += VT[r * 64 + f + 2] * Wo[(f + 2) * 64 + g];
                    a3 += VT[r * 64 + f + 3] * Wo[(f + 3) * 64 + g];
                }
                g_T[3][(base + 80 * (k0 + r)) * 64 + g] = (a0 + a1) + (a2 + a3);
            }
            __threadfence();
            __syncthreads();
            if (t < nr) atomicExch(&g_seal[base + 80 * (k0 + t)], 1);
            __syncthreads();
        }
        return;
    }

    // ================= worker blocks =================
    int* hist     = sm;
    int* hashA    = hist + 2000;
    int* hashO    = hashA + HSZ;
    int* a_keys   = hashO + HSZ;
    int* o_keys   = a_keys + 512;
    int* o_mult   = o_keys + 512;
    int* counters = o_mult + 512;          // [0]=n_ap [1]=n_op [3]=n_cnt
    int* marks    = counters + 8;          // 17 ints: bitmap counts 0..543
    int* cvals    = counters + 32;         // [64]
    unsigned short* tok_as = (unsigned short*)(counters + 96);
    float* ctx2q  = (float*)(counters + 96 + 256);
    float* Ebuf   = ctx2q + 4096;
    float* Vbuf   = Ebuf + 2048;
    float* colmax = Vbuf + 2048;
    float* part   = colmax + 64;
    float* cvec   = part + 256;
    float* outrows = Ebuf;                 // 4096 floats (spans Ebuf+Vbuf)

    const int bid1 = blockIdx.x - NBUILD;
    const int dir = bid1 >> 8;
    const int b = bid1 & 255;
    const int* a_ids = (dir == 0 ? src : dst) + b * 512;
    const int* o_ids = (dir == 0 ? dst : src) + b * 512;

    // ---- init ----
    {
        int4* z = (int4*)hist;
        for (int i = t; i < 500; i += 256) z[i] = make_int4(0, 0, 0, 0);
        int4* hneg = (int4*)hashA;
        for (int i = t; i < 256; i += 256) hneg[i] = make_int4(-1, -1, -1, -1);
        int4* zm = (int4*)o_mult;
        for (int i = t; i < 128; i += 256) zm[i] = make_int4(0, 0, 0, 0);
    }
    if (t < 96) counters[t] = 0;
    if (t < 128) cvec[t] = (t < 64) ? lng[t] : lnb[t - 64];
    __syncthreads();

    // ---- packed histograms: a-count low16, o-count high16 ----
    const int av0 = a_ids[t], av1 = a_ids[t + 256];
    const int ov0 = o_ids[t], ov1 = o_ids[t + 256];
    atomicAdd(&hist[av0], 1);
    atomicAdd(&hist[av1], 1);
    atomicAdd(&hist[ov0], 1 << 16);
    atomicAdd(&hist[ov1], 1 << 16);
    __syncthreads();

    // ---- per-token count pairs -> warp-aggregated dedupe ----
#pragma unroll
    for (int rep = 0; rep < 2; rep++) {
        const int l = t + rep * 256;
        const int av = rep ? av1 : av0, ov = rep ? ov1 : ov0;
        int ha = hist[av];
        int akey = av ? (((ha & 0xFFFF) << 10) | (ha >> 16)) : 0;
        tok_as[l] = (unsigned short)insert_pair_agg(akey, hashA, &counters[0], a_keys, 0);
        int ho = hist[ov];
        int okey = ov ? (((ho >> 16) << 10) | (ho & 0xFFFF)) : 0;
        insert_pair_agg(okey, hashO, &counters[1], o_keys, o_mult);
    }
    __syncthreads();
    const int n_ap = counters[0], n_op = counters[1];

    // ---- mark distinct count values (provably <= 63) ----
    for (int p = t; p < n_ap; p += 256) {
        int k = a_keys[p], i0 = k >> 10, i1 = k & 1023;
        atomicOr(&marks[i0 >> 5], 1u << (i0 & 31));
        atomicOr(&marks[i1 >> 5], 1u << (i1 & 31));
    }
    for (int p = t; p < n_op; p += 256) {
        int k = o_keys[p], i0 = k >> 10, i1 = k & 1023;
        atomicOr(&marks[i0 >> 5], 1u << (i0 & 31));
        atomicOr(&marks[i1 >> 5], 1u << (i1 & 31));
    }
    __syncthreads();
    for (int i = t; i <= 512; i += 256) {
        if (marks[i >> 5] & (1u << (i & 31))) {
            int s = atomicAdd(&counters[3], 1);
            if (s < 64) cvals[s] = i;
        }
    }
    __syncthreads();
    const int nc = min(counters[3], 64);

    // ---- wait for the table rows we need (hot rows sealed early) ----
    if (t < nc) {
        int c = cvals[t];
        while (atomicOr(&g_seal[c], 0) == 0) __nanosleep(32);
        __threadfence();
    }
    __syncthreads();

    // ---- softmax shift: colmax[d] = 2 * max over present counts of Tk ----
    const float* Tk = g_T[2];
    if (t < 64) {
        float m = -3.4e38f;
        for (int j = 0; j < nc; j++) m = fmaxf(m, Tk[cvals[j] * 64 + t]);
        colmax[t] = 2.0f * m;
    }
    __syncthreads();

    // ---- Phase B: ctx2[d][g] = colinv[d] * sum_p E[p][d] * VWo[p][g] ----
    const float* Tvo = g_T[3];
    {
        const int dbase = (t >> 4) << 2, ebase = (t & 15) << 2;
        float acc[4][4] = {};
        float esum[4] = {};
        for (int pc = 0; pc < n_op; pc += 32) {
            const int cn = min(32, n_op - pc);
            for (int idx = t; idx < cn * 16; idx += 256) {
                int p = idx >> 4, d4 = (idx & 15) << 2;
                int key = o_keys[pc + p], i0 = key >> 10, i1 = key & 1023;
                float4 k0 = *(const float4*)&Tk[i0 * 64 + d4];
                float4 k1 = *(const float4*)&Tk[i1 * 64 + d4];
                float4 cm = *(const float4*)&colmax[d4];
                float mlt = (float)o_mult[pc + p];
                float4 e;
                e.x = mlt * __expf(k0.x + k1.x - cm.x);
                e.y = mlt * __expf(k0.y + k1.y - cm.y);
                e.z = mlt * __expf(k0.z + k1.z - cm.z);
                e.w = mlt * __expf(k0.w + k1.w - cm.w);
                *(float4*)&Ebuf[p * 64 + d4] = e;
            }
            for (int idx = t; idx < cn * 16; idx += 256) {
                int p = idx >> 4, e4 = (idx & 15) << 2;
                int key = o_keys[pc + p], i0 = key >> 10, i1 = key & 1023;
                float4 v0 = *(const float4*)&Tvo[i0 * 64 + e4];
                float4 v1 = *(const float4*)&Tvo[i1 * 64 + e4];
                float4 v;
                v.x = v0.x + v1.x; v.y = v0.y + v1.y;
                v.z = v0.z + v1.z; v.w = v0.w + v1.w;
                *(float4*)&Vbuf[p * 64 + e4] = v;
            }
            __syncthreads();
            for (int p = 0; p < cn; p++) {
                float4 ev = *(const float4*)&Ebuf[p * 64 + dbase];
                float4 vv = *(const float4*)&Vbuf[p * 64 + ebase];
                float e_[4] = {ev.x, ev.y, ev.z, ev.w};
                float v_[4] = {vv.x, vv.y, vv.z, vv.w};
#pragma unroll
                for (int i = 0; i < 4; i++)
#pragma unroll
                    for (int j = 0; j < 4; j++) acc[i][j] += e_[i] * v_[j];
                if (ebase == 0) {
#pragma unroll
                    for (int i = 0; i < 4; i++) esum[i] += e_[i];
                }
            }
            __syncthreads();
        }
        if (ebase == 0) {
#pragma unroll
            for (int i = 0; i < 4; i++) part[dbase + i] = esum[i];
        }
        __syncthreads();
        // float4-packed ctx2: entry (d*32+e)*4 + comp, d,e in 0..31
        // comp: 0=(d,e) 1=(d,e+32) 2=(d+32,e) 3=(d+32,e+32)
        const int dd = dbase & 31, hi = (dbase >> 5) << 1;
        const int el = ebase & 31, eh = ebase >> 5;
#pragma unroll
        for (int i = 0; i < 4; i++) {
            float inv = 1.0f / part[dbase + i];
#pragma unroll
            for (int j = 0; j < 4; j++)
                ctx2q[((dd + i) * 32 + el + j) * 4 + hi + eh] = acc[i][j] * inv;
        }
    }
    __syncthreads();

    // ---- Phase C: per unique a-pair: q softmax -> attn -> +feat -> LN ----
    const float* Tq = g_T[1];
    const float* Tf = g_T[0];
    {
        const int w = t >> 5, lane = t & 31;
        const float g0 = cvec[lane], g1 = cvec[32 + lane];
        const float be0 = cvec[64 + lane], be1 = cvec[96 + lane];
        const size_t outbase = (((size_t)dir * 256 + b) * 512) * 64;

        for (int ac = 0; ac < n_ap; ac += 64) {
            const int an = min(64, n_ap - ac);
            for (int p = w; p < an; p += 8) {
                int key = a_keys[ac + p], i0 = key >> 10, i1 = key & 1023;
                float q0 = Tq[i0 * 64 + lane] + Tq[i1 * 64 + lane];
                float q1 = Tq[i0 * 64 + 32 + lane] + Tq[i1 * 64 + 32 + lane];
                float f0 = Tf[i0 * 64 + lane] + Tf[i1 * 64 + lane];
                float f1 = Tf[i0 * 64 + 32 + lane] + Tf[i1 * 64 + 32 + lane];
                float m = fmaxf(q0, q1);
#pragma unroll
                for (int off = 16; off; off >>= 1) m = fmaxf(m, __shfl_xor_sync(~0u, m, off));
                float e0 = __expf(q0 - m), e1 = __expf(q1 - m);
                float s = e0 + e1;
#pragma unroll
                for (int off = 16; off; off >>= 1) s += __shfl_xor_sync(~0u, s, off);
                float coef = 0.125f / s;          // F^-0.5 / sum
                float e0c = e0 * coef, e1c = e1 * coef;
                float a0 = 0.f, a1 = 0.f;
#pragma unroll 8
                for (int d = 0; d < 32; d++) {
                    float qlo = __shfl_sync(~0u, e0c, d);
                    float qhi = __shfl_sync(~0u, e1c, d);
                    float4 cp = *(const float4*)&ctx2q[(d * 32 + lane) * 4];
                    a0 += qlo * cp.x + qhi * cp.z;
                    a1 += qlo * cp.y + qhi * cp.w;
                }
                float y0 = f0 + a0;               // bo folded into Tf
                float y1 = f1 + a1;
                float mu = y0 + y1;
#pragma unroll
                for (int off = 16; off; off >>= 1) mu += __shfl_xor_sync(~0u, mu, off);
                mu *= (1.0f / 64.0f);
                float dy0 = y0 - mu, dy1 = y1 - mu;
                float var = dy0 * dy0 + dy1 * dy1;
#pragma unroll
                for (int off = 16; off; off >>= 1) var += __shfl_xor_sync(~0u, var, off);
                var *= (1.0f / 64.0f);
                float rs = rsqrtf(var + 1e-5f);
                outrows[p * 64 + lane]      = dy0 * rs * g0 + be0;
                outrows[p * 64 + 32 + lane] = dy1 * rs * g1 + be1;
            }
            __syncthreads();
            // scatter: 2 tokens per warp per iteration; streaming stores
            {
                const int half = lane >> 4, q = lane & 15;
                for (int l = w * 2 + half; l < 512; l += 16) {
                    int s = (int)tok_as[l] - ac;
                    if ((unsigned)s < (unsigned)an) {
                        float4 v = *(const float4*)&outrows[s * 64 + q * 4];
                        __stcs((float4*)&out[outbase + (size_t)l * 64 + q * 4], v);
                    }
                }
            }
            __syncthreads();
        }
    }
}

// ---------------------------------------------------------------------------
extern "C" void kernel_launch(void* const* d_in, const int* in_sizes, int n_in,
                              void* d_out, int out_size)
{
    const int*   src = (const int*)d_in[0];
    const int*   dst = (const int*)d_in[1];
    const float* w1  = (const float*)d_in[2];
    const float* b1  = (const float*)d_in[3];
    const float* w2  = (const float*)d_in[4];
    const float* b2  = (const float*)d_in[5];
    const float* Wq  = (const float*)d_in[6];
    const float* Wk  = (const float*)d_in[7];
    const float* Wv  = (const float*)d_in[8];
    const float* Wo  = (const float*)d_in[9];
    const float* bo  = (const float*)d_in[10];
    const float* lng = (const float*)d_in[11];
    const float* lnb = (const float*)d_in[12];
    float* out = (float*)d_out;

    cudaFuncSetAttribute(fused_kernel, cudaFuncAttributeMaxDynamicSharedMemorySize, SMEM_BYTES);
    fused_kernel<<<NBUILD + 512, 256, SMEM_BYTES>>>(
        src, dst, w1, b1, w2, b2, Wq, Wk, Wv, Wo, bo, lng, lnb, out);
}

// round 17
// speedup vs baseline: 1.0743x; 1.0743x over previous
#include <cuda_runtime.h>

#define HSZ  512
#define TMAX 513
#define NBUILD 64

// tables: 0=feat(+bo/2), 1=q, 2=k, 3=v@Wo   (token row = T[c0] + T[c1])
__device__ float g_T[4][TMAX * 64];
__device__ int g_seal[TMAX];   // zero-init; 1 once row c is written

// ---------------------------------------------------------------------------
// Packed hash entry: (key << 10) | slot.  EMPTY = -1, PENDING slot = 0x3FF.
__device__ __forceinline__ int insert_pair(int key, int* tab, int* counter, int* keys)
{
    unsigned h = ((unsigned)key * 2654435761u) >> 23;   // 9-bit hash
    const int PEND = (key << 10) | 0x3FF;
    while (true) {
        int e = tab[h];
        if (e == -1) e = atomicCAS(&tab[h], -1, PEND);
        if (e == -1) {
            int s = atomicAdd(counter, 1);
            keys[s] = key;
            __threadfence_block();
            atomicExch(&tab[h], (key << 10) | s);
            return s;
        }
        if ((e >> 10) == key) {
            int s = e & 0x3FF;
            while (s == 0x3FF) s = ((volatile int*)tab)[h] & 0x3FF;
            return s;
        }
        h = (h + 1) & (HSZ - 1);
    }
}

__device__ __forceinline__ int insert_pair_agg(int key, int* tab, int* counter,
                                               int* keys, int* mult)
{
    unsigned peers = __match_any_sync(0xffffffffu, key);
    int leader = __ffs(peers) - 1;
    int s = 0;
    if ((int)(threadIdx.x & 31) == leader) {
        s = insert_pair(key, tab, counter, keys);
        if (mult) atomicAdd(&mult[s], __popc(peers));
    }
    return __shfl_sync(0xffffffffu, s, leader);
}

// Shared plan (worker): hist[2000] hashA[512] hashO[512] a_keys[512] o_keys[512]
//   o_mult[512] counters[96] (ctr8+marks17+pad+cvals64) tok_as u16[512]
//   ctx2q[4096] Ebuf[2048] Vbuf[2048] colmax[64] part[256] cvec[128]
#define NINT (2000 + 2 * HSZ + 3 * 512 + 96 + 256)
#define NFLT (4096 + 2048 + 2048 + 64 + 256 + 128)
#define SMEM_BYTES ((NINT + NFLT) * 4)

__global__ void __launch_bounds__(256, 4) fused_kernel(
    const int* __restrict__ src, const int* __restrict__ dst,
    const float* __restrict__ w1, const float* __restrict__ b1,
    const float* __restrict__ w2, const float* __restrict__ b2,
    const float* __restrict__ Wq, const float* __restrict__ Wk,
    const float* __restrict__ Wv, const float* __restrict__ Wo,
    const float* __restrict__ bo,
    const float* __restrict__ lng, const float* __restrict__ lnb,
    float* __restrict__ out)
{
    extern __shared__ int sm[];
    const int t = threadIdx.x;

    // ================= builder blocks (0..63): 8-9 rows each, batched =======
    if (blockIdx.x < NBUILD) {
        float* R  = (float*)sm;         // 9*64
        float* FE = R + 576;            // 9*64
        float* VT = FE + 576;           // 9*64
        const int g = t & 63, j = t >> 6;            // j in 0..3
        const int base = blockIdx.x;                 // rows c = base + 64*k
        const int nr = (blockIdx.x == 0) ? 9 : 8;    // block 0 also does c=512

        for (int idx = t; idx < nr * 64; idx += 256) {
            int k = idx >> 6, f = idx & 63;
            R[idx] = fmaxf((float)(base + 64 * k) * w1[f] + b1[f], 0.f);
        }
        __syncthreads();
        for (int r = j; r < nr; r += 4) {
            float a0 = 0.f, a1 = 0.f, a2 = 0.f, a3 = 0.f;
#pragma unroll
            for (int f = 0; f < 64; f += 4) {
                a0 += R[r * 64 + f]     * w2[f * 64 + g];
                a1 += R[r * 64 + f + 1] * w2[(f + 1) * 64 + g];
                a2 += R[r * 64 + f + 2] * w2[(f + 2) * 64 + g];
                a3 += R[r * 64 + f + 3] * w2[(f + 3) * 64 + g];
            }
            float acc = b2[g] + ((a0 + a1) + (a2 + a3));
            FE[r * 64 + g] = acc;
            g_T[0][(base + 64 * r) * 64 + g] = acc + 0.5f * bo[g];
        }
        __syncthreads();
        for (int r = j; r < nr; r += 4) {
            float aq = 0.f, ak = 0.f, av = 0.f;
#pragma unroll 8
            for (int f = 0; f < 64; f++) {
                float fe = FE[r * 64 + f];
                aq += fe * Wq[f * 64 + g];
                ak += fe * Wk[f * 64 + g];
                av += fe * Wv[f * 64 + g];
            }
            int c = base + 64 * r;
            g_T[1][c * 64 + g] = aq;
            g_T[2][c * 64 + g] = ak;
            VT[r * 64 + g] = av;
        }
        __syncthreads();
        for (int r = j; r < nr; r += 4) {
            float a0 = 0.f, a1 = 0.f, a2 = 0.f, a3 = 0.f;
#pragma unroll
            for (int f = 0; f < 64; f += 4) {
                a0 += VT[r * 64 + f]     * Wo[f * 64 + g];
                a1 += VT[r * 64 + f + 1] * Wo[(f + 1) * 64 + g];
                a2 += VT[r * 64 + f + 2] * Wo[(f + 2) * 64 + g];
                a3 += VT[r * 64 + f + 3] * Wo[(f + 3) * 64 + g];
            }
            g_T[3][(base + 64 * r) * 64 + g] = (a0 + a1) + (a2 + a3);
        }
        __threadfence();
        __syncthreads();
        if (t < nr) atomicExch(&g_seal[base + 64 * t], 1);
        return;
    }

    // ================= worker blocks =================
    int* hist     = sm;
    int* hashA    = hist + 2000;
    int* hashO    = hashA + HSZ;
    int* a_keys   = hashO + HSZ;
    int* o_keys   = a_keys + 512;
    int* o_mult   = o_keys + 512;
    int* counters = o_mult + 512;          // [0]=n_ap [1]=n_op [3]=n_cnt
    int* marks    = counters + 8;          // 17 ints: bitmap counts 0..543
    int* cvals    = counters + 32;         // [64]
    unsigned short* tok_as = (unsigned short*)(counters + 96);
    float* ctx2q  = (float*)(counters + 96 + 256);
    float* Ebuf   = ctx2q + 4096;
    float* Vbuf   = Ebuf + 2048;
    float* colmax = Vbuf + 2048;
    float* part   = colmax + 64;
    float* cvec   = part + 256;
    float* outrows = Ebuf;                 // 4096 floats (spans Ebuf+Vbuf)

    const int bid1 = blockIdx.x - NBUILD;
    const int dir = bid1 >> 8;
    const int b = bid1 & 255;
    const int* a_ids = (dir == 0 ? src : dst) + b * 512;
    const int* o_ids = (dir == 0 ? dst : src) + b * 512;

    // ---- init ----
    {
        int4* z = (int4*)hist;
        for (int i = t; i < 500; i += 256) z[i] = make_int4(0, 0, 0, 0);
        int4* hneg = (int4*)hashA;
        for (int i = t; i < 256; i += 256) hneg[i] = make_int4(-1, -1, -1, -1);
        int4* zm = (int4*)o_mult;
        for (int i = t; i < 128; i += 256) zm[i] = make_int4(0, 0, 0, 0);
    }
    if (t < 96) counters[t] = 0;
    if (t < 128) cvec[t] = (t < 64) ? lng[t] : lnb[t - 64];
    __syncthreads();

    // ---- packed histograms: a-count low16, o-count high16 ----
    const int av0 = a_ids[t], av1 = a_ids[t + 256];
    const int ov0 = o_ids[t], ov1 = o_ids[t + 256];
    atomicAdd(&hist[av0], 1);
    atomicAdd(&hist[av1], 1);
    atomicAdd(&hist[ov0], 1 << 16);
    atomicAdd(&hist[ov1], 1 << 16);
    __syncthreads();

    // ---- per-token count pairs -> warp-aggregated dedupe ----
#pragma unroll
    for (int rep = 0; rep < 2; rep++) {
        const int l = t + rep * 256;
        const int av = rep ? av1 : av0, ov = rep ? ov1 : ov0;
        int ha = hist[av];
        int akey = av ? (((ha & 0xFFFF) << 10) | (ha >> 16)) : 0;
        tok_as[l] = (unsigned short)insert_pair_agg(akey, hashA, &counters[0], a_keys, 0);
        int ho = hist[ov];
        int okey = ov ? (((ho >> 16) << 10) | (ho & 0xFFFF)) : 0;
        insert_pair_agg(okey, hashO, &counters[1], o_keys, o_mult);
    }
    __syncthreads();
    const int n_ap = counters[0], n_op = counters[1];

    // ---- mark distinct count values (provably <= 63) ----
    for (int p = t; p < n_ap; p += 256) {
        int k = a_keys[p], i0 = k >> 10, i1 = k & 1023;
        atomicOr(&marks[i0 >> 5], 1u << (i0 & 31));
        atomicOr(&marks[i1 >> 5], 1u << (i1 & 31));
    }
    for (int p = t; p < n_op; p += 256) {
        int k = o_keys[p], i0 = k >> 10, i1 = k & 1023;
        atomicOr(&marks[i0 >> 5], 1u << (i0 & 31));
        atomicOr(&marks[i1 >> 5], 1u << (i1 & 31));
    }
    __syncthreads();
    for (int i = t; i <= 512; i += 256) {
        if (marks[i >> 5] & (1u << (i & 31))) {
            int s = atomicAdd(&counters[3], 1);
            if (s < 64) cvals[s] = i;
        }
    }
    __syncthreads();
    const int nc = min(counters[3], 64);

    // ---- wait for the table rows we need (builders finish ~2us in) ----
    if (t < nc) {
        int c = cvals[t];
        while (atomicOr(&g_seal[c], 0) == 0) __nanosleep(32);
        __threadfence();
    }
    __syncthreads();

    // ---- softmax shift: colmax[d] = 2 * max over present counts of Tk ----
    const float* Tk = g_T[2];
    if (t < 64) {
        float m = -3.4e38f;
        for (int j = 0; j < nc; j++) m = fmaxf(m, Tk[cvals[j] * 64 + t]);
        colmax[t] = 2.0f * m;
    }
    __syncthreads();

    // ---- Phase B: ctx2[d][g] = colinv[d] * sum_p E[p][d] * VWo[p][g] ----
    const float* Tvo = g_T[3];
    {
        const int dbase = (t >> 4) << 2, ebase = (t & 15) << 2;
        float acc[4][4] = {};
        float esum[4] = {};
        for (int pc = 0; pc < n_op; pc += 32) {
            const int cn = min(32, n_op - pc);
            for (int idx = t; idx < cn * 16; idx += 256) {
                int p = idx >> 4, d4 = (idx & 15) << 2;
                int key = o_keys[pc + p], i0 = key >> 10, i1 = key & 1023;
                float4 k0 = *(const float4*)&Tk[i0 * 64 + d4];
                float4 k1 = *(const float4*)&Tk[i1 * 64 + d4];
                float4 cm = *(const float4*)&colmax[d4];
                float mlt = (float)o_mult[pc + p];
                float4 e;
                e.x = mlt * __expf(k0.x + k1.x - cm.x);
                e.y = mlt * __expf(k0.y + k1.y - cm.y);
                e.z = mlt * __expf(k0.z + k1.z - cm.z);
                e.w = mlt * __expf(k0.w + k1.w - cm.w);
                *(float4*)&Ebuf[p * 64 + d4] = e;
            }
            for (int idx = t; idx < cn * 16; idx += 256) {
                int p = idx >> 4, e4 = (idx & 15) << 2;
                int key = o_keys[pc + p], i0 = key >> 10, i1 = key & 1023;
                float4 v0 = *(const float4*)&Tvo[i0 * 64 + e4];
                float4 v1 = *(const float4*)&Tvo[i1 * 64 + e4];
                float4 v;
                v.x = v0.x + v1.x; v.y = v0.y + v1.y;
                v.z = v0.z + v1.z; v.w = v0.w + v1.w;
                *(float4*)&Vbuf[p * 64 + e4] = v;
            }
            __syncthreads();
            for (int p = 0; p < cn; p++) {
                float4 ev = *(const float4*)&Ebuf[p * 64 + dbase];
                float4 vv = *(const float4*)&Vbuf[p * 64 + ebase];
                float e_[4] = {ev.x, ev.y, ev.z, ev.w};
                float v_[4] = {vv.x, vv.y, vv.z, vv.w};
#pragma unroll
                for (int i = 0; i < 4; i++)
#pragma unroll
                    for (int j = 0; j < 4; j++) acc[i][j] += e_[i] * v_[j];
                if (ebase == 0) {
#pragma unroll
                    for (int i = 0; i < 4; i++) esum[i] += e_[i];
                }
            }
            __syncthreads();
        }
        if (ebase == 0) {
#pragma unroll
            for (int i = 0; i < 4; i++) part[dbase + i] = esum[i];
        }
        __syncthreads();
        // float4-packed ctx2: entry (d*32+e)*4 + comp, d,e in 0..31
        // comp: 0=(d,e) 1=(d,e+32) 2=(d+32,e) 3=(d+32,e+32)
        const int dd = dbase & 31, hi = (dbase >> 5) << 1;
        const int el = ebase & 31, eh = ebase >> 5;
#pragma unroll
        for (int i = 0; i < 4; i++) {
            float inv = 1.0f / part[dbase + i];
#pragma unroll
            for (int j = 0; j < 4; j++)
                ctx2q[((dd + i) * 32 + el + j) * 4 + hi + eh] = acc[i][j] * inv;
        }
    }
    __syncthreads();

    // ---- Phase C: per unique a-pair: q softmax -> attn -> +feat -> LN ----
    const float* Tq = g_T[1];
    const float* Tf = g_T[0];
    {
        const int w = t >> 5, lane = t & 31;
        const float g0 = cvec[lane], g1 = cvec[32 + lane];
        const float be0 = cvec[64 + lane], be1 = cvec[96 + lane];
        const size_t outbase = (((size_t)dir * 256 + b) * 512) * 64;

        for (int ac = 0; ac < n_ap; ac += 64) {
            const int an = min(64, n_ap - ac);
            for (int p = w; p < an; p += 8) {
                int key = a_keys[ac + p], i0 = key >> 10, i1 = key & 1023;
                float q0 = Tq[i0 * 64 + lane] + Tq[i1 * 64 + lane];
                float q1 = Tq[i0 * 64 + 32 + lane] + Tq[i1 * 64 + 32 + lane];
                float f0 = Tf[i0 * 64 + lane] + Tf[i1 * 64 + lane];
                float f1 = Tf[i0 * 64 + 32 + lane] + Tf[i1 * 64 + 32 + lane];
                float m = fmaxf(q0, q1);
#pragma unroll
                for (int off = 16; off; off >>= 1) m = fmaxf(m, __shfl_xor_sync(~0u, m, off));
                float e0 = __expf(q0 - m), e1 = __expf(q1 - m);
                float s = e0 + e1;
#pragma unroll
                for (int off = 16; off; off >>= 1) s += __shfl_xor_sync(~0u, s, off);
                float coef = 0.125f / s;          // F^-0.5 / sum
                float e0c = e0 * coef, e1c = e1 * coef;
                float a0 = 0.f, a1 = 0.f;
#pragma unroll 8
                for (int d = 0; d < 32; d++) {
                    float qlo = __shfl_sync(~0u, e0c, d);
                    float qhi = __shfl_sync(~0u, e1c, d);
                    float4 cp = *(const float4*)&ctx2q[(d * 32 + lane) * 4];
                    a0 += qlo * cp.x + qhi * cp.z;
                    a1 += qlo * cp.y + qhi * cp.w;
                }
                float y0 = f0 + a0;               // bo folded into Tf
                float y1 = f1 + a1;
                float mu = y0 + y1;
#pragma unroll
                for (int off = 16; off; off >>= 1) mu += __shfl_xor_sync(~0u, mu, off);
                mu *= (1.0f / 64.0f);
                float dy0 = y0 - mu, dy1 = y1 - mu;
                float var = dy0 * dy0 + dy1 * dy1;
#pragma unroll
                for (int off = 16; off; off >>= 1) var += __shfl_xor_sync(~0u, var, off);
                var *= (1.0f / 64.0f);
                float rs = rsqrtf(var + 1e-5f);
                outrows[p * 64 + lane]      = dy0 * rs * g0 + be0;
                outrows[p * 64 + 32 + lane] = dy1 * rs * g1 + be1;
            }
            __syncthreads();
            // scatter: 2 tokens per warp per iteration; streaming stores
            {
                const int half = lane >> 4, q = lane & 15;
                for (int l = w * 2 + half; l < 512; l += 16) {
                    int s = (int)tok_as[l] - ac;
                    if ((unsigned)s < (unsigned)an) {
                        float4 v = *(const float4*)&outrows[s * 64 + q * 4];
                        __stcs((float4*)&out[outbase + (size_t)l * 64 + q * 4], v);
                    }
                }
            }
            __syncthreads();
        }
    }
}

// ---------------------------------------------------------------------------
extern "C" void kernel_launch(void* const* d_in, const int* in_sizes, int n_in,
                              void* d_out, int out_size)
{
    const int*   src = (const int*)d_in[0];
    const int*   dst = (const int*)d_in[1];
    const float* w1  = (const float*)d_in[2];
    const float* b1  = (const float*)d_in[3];
    const float* w2  = (const float*)d_in[4];
    const float* b2  = (const float*)d_in[5];
    const float* Wq  = (const float*)d_in[6];
    const float* Wk  = (const float*)d_in[7];
    const float* Wv  = (const float*)d_in[8];
    const float* Wo  = (const float*)d_in[9];
    const float* bo  = (const float*)d_in[10];
    const float* lng = (const float*)d_in[11];
    const float* lnb = (const float*)d_in[12];
    float* out = (float*)d_out;

    cudaFuncSetAttribute(fused_kernel, cudaFuncAttributeMaxDynamicSharedMemorySize, SMEM_BYTES);
    fused_kernel<<<NBUILD + 512, 256, SMEM_BYTES>>>(
        src, dst, w1, b1, w2, b2, Wq, Wk, Wv, Wo, bo, lng, lnb, out);
}